// round 2
// baseline (speedup 1.0000x reference)
#include <cuda_runtime.h>
#include <math.h>

// RITS recurrent imputation. B=1024, T=128, D=64, H=256.
// Batch-split persistent kernel: each CTA owns MB=8 batch rows, runs the
// full T-step recurrence locally. No inter-CTA communication needed.
// Small weights resident in SMEM (pre-transposed); lstm_k/lstm_rk stream
// from L2 (fully coalesced, 8-row reuse per load).

#define Bc 1024
#define Tc 128
#define Dc 64
#define Hc 256
#define MB 8
#define NT 256

// shared layout (floats)
#define OF_TDHWT 0                      // 64x256 (transposed td_h_W)
#define OF_HISTW (OF_TDHWT + 16384)     // 256x64
#define OF_TXWT  (OF_HISTW + 16384)     // 64x64 (transposed td_x_W)
#define OF_FRWT  (OF_TXWT + 4096)      // 64x64 (transposed fr_W)
#define OF_WCW   (OF_FRWT + 4096)      // 128x64
#define OF_BHS   (OF_WCW + 8192)       // 256 td_h_b
#define OF_BXS   (OF_BHS + 256)        // 64
#define OF_BHIST (OF_BXS + 64)         // 64
#define OF_BFR   (OF_BHIST + 64)       // 64
#define OF_BWC   (OF_BFR + 64)         // 64
#define OF_H     (OF_BWC + 64)         // 8x256
#define OF_X     (OF_H + 2048)         // 8x64
#define OF_M     (OF_X + 512)          // 8x64
#define OF_D     (OF_M + 512)          // 8x64
#define OF_INP   (OF_D + 512)          // 8x128
#define OF_XH    (OF_INP + 1024)       // 8x64
#define OF_XC    (OF_XH + 512)         // 8x64
#define OF_GX    (OF_XC + 512)         // 8x64
#define OF_RED   (OF_GX + 512)         // 32
#define SMEM_FLOATS (OF_RED + 32)
#define SMEM_BYTES (SMEM_FLOATS * 4)

__device__ __forceinline__ float sigf(float x) { return 1.0f / (1.0f + expf(-x)); }

extern "C" __global__ void __launch_bounds__(NT, 1)
rits_kernel(const float* __restrict__ values, const float* __restrict__ masks,
            const float* __restrict__ deltas,
            const float* __restrict__ td_h_W, const float* __restrict__ td_h_b,
            const float* __restrict__ td_x_W, const float* __restrict__ td_x_b,
            const float* __restrict__ hist_W, const float* __restrict__ hist_b,
            const float* __restrict__ fr_W, const float* __restrict__ fr_b,
            const float* __restrict__ wc_W, const float* __restrict__ wc_b,
            const float* __restrict__ lstm_k, const float* __restrict__ lstm_rk,
            const float* __restrict__ lstm_b,
            const float* __restrict__ out_W, const float* __restrict__ out_b,
            float* __restrict__ out)
{
    extern __shared__ float sm[];
    float* tdhWT = sm + OF_TDHWT;
    float* histWs = sm + OF_HISTW;
    float* txWT = sm + OF_TXWT;
    float* frWT = sm + OF_FRWT;
    float* wcWs = sm + OF_WCW;
    float* bhs = sm + OF_BHS;
    float* bxs = sm + OF_BXS;
    float* bhist = sm + OF_BHIST;
    float* bfr = sm + OF_BFR;
    float* bwc = sm + OF_BWC;
    float* h_s = sm + OF_H;
    float* x_s = sm + OF_X;
    float* m_s = sm + OF_M;
    float* d_s = sm + OF_D;
    float* inp_s = sm + OF_INP;
    float* xh_s = sm + OF_XH;
    float* xc_s = sm + OF_XC;
    float* gx_s = sm + OF_GX;
    float* red_s = sm + OF_RED;

    const int tid = threadIdx.x;
    const int b0 = blockIdx.x * MB;

    // ---- preload small weights into SMEM (transposed where needed) ----
    for (int idx = tid; idx < Hc * Dc; idx += NT) {   // td_h_W [H,D] -> [D,H]
        int j = idx >> 6, k = idx & 63;
        tdhWT[k * Hc + j] = td_h_W[idx];
    }
    for (int idx = tid; idx < Hc * Dc; idx += NT)     // hist_W [H,D] as-is
        histWs[idx] = hist_W[idx];
    for (int idx = tid; idx < Dc * Dc; idx += NT) {   // td_x_W [D,D] -> T
        int i = idx >> 6, k = idx & 63;
        txWT[k * Dc + i] = td_x_W[idx];
    }
    for (int idx = tid; idx < Dc * Dc; idx += NT) {   // fr_W [D,D] -> T
        int i = idx >> 6, k = idx & 63;
        frWT[k * Dc + i] = fr_W[idx];
    }
    for (int idx = tid; idx < 2 * Dc * Dc; idx += NT) // wc_W [2D,D] as-is
        wcWs[idx] = wc_W[idx];
    bhs[tid] = td_h_b[tid];
    if (tid < 64) {
        bxs[tid] = td_x_b[tid];
        bhist[tid] = hist_b[tid];
        bfr[tid] = fr_b[tid];
        bwc[tid] = wc_b[tid];
    }
    // init state
    #pragma unroll
    for (int r = 0; r < MB; r++) h_s[r * Hc + tid] = 0.0f;
    float c_reg[MB];
    #pragma unroll
    for (int r = 0; r < MB; r++) c_reg[r] = 0.0f;
    __syncthreads();

    const float bls0 = lstm_b[tid];
    const float bls1 = lstm_b[256 + tid];
    const float bls2 = lstm_b[512 + tid];
    const float bls3 = lstm_b[768 + tid];

    float* out_y = out;
    float* out_imp = out + Bc;

    for (int t = 0; t < Tc; t++) {
        // ---- load x, m, d for this CTA's 8 rows ----
        {
            int e = tid;
            #pragma unroll
            for (int p = 0; p < 2; p++, e += NT) {
                int r = e >> 6, dc = e & 63;
                long gi = ((long)(b0 + r) * Tc + t) * Dc + dc;
                x_s[e] = values[gi];
                m_s[e] = masks[gi];
                d_s[e] = deltas[gi];
            }
        }
        __syncthreads();

        // ---- gamma_h = exp(-relu(d @ td_h_W^T + b)); h *= gamma_h ----
        // thread tid owns hidden column tid
        #pragma unroll
        for (int r = 0; r < MB; r++) {
            float s = bhs[tid];
            #pragma unroll 8
            for (int k = 0; k < Dc; k++)
                s += d_s[r * Dc + k] * tdhWT[k * Hc + tid];
            float gh = expf(-fmaxf(s, 0.0f));
            h_s[r * Hc + tid] *= gh;
        }
        __syncthreads();

        // ---- x_h = h @ hist_W + b; x_c; gamma_x ----
        {
            const int i = tid & 63;
            const int rb = tid >> 6;
            #pragma unroll
            for (int rr = 0; rr < 2; rr++) {
                int r = rb + 4 * rr;
                float s = bhist[i];
                #pragma unroll 8
                for (int j = 0; j < Hc; j++)
                    s += h_s[r * Hc + j] * histWs[j * Dc + i];
                float mm = m_s[r * Dc + i];
                float xc = mm * x_s[r * Dc + i] + (1.0f - mm) * s;
                xh_s[r * Dc + i] = s;
                xc_s[r * Dc + i] = xc;
                float s2 = bxs[i];
                #pragma unroll 8
                for (int k = 0; k < Dc; k++)
                    s2 += d_s[r * Dc + k] * txWT[k * Dc + i];
                gx_s[r * Dc + i] = expf(-fmaxf(s2, 0.0f));
            }
        }
        __syncthreads();

        // ---- z_h, alpha, c_h, c_c, write imputation, build inp ----
        {
            const int i = tid & 63;
            const int rb = tid >> 6;
            #pragma unroll
            for (int rr = 0; rr < 2; rr++) {
                int r = rb + 4 * rr;
                float zh = bfr[i];
                #pragma unroll 8
                for (int k = 0; k < Dc; k++)
                    zh += xc_s[r * Dc + k] * frWT[k * Dc + i];
                float al = bwc[i];
                #pragma unroll 8
                for (int k = 0; k < Dc; k++)
                    al += gx_s[r * Dc + k] * wcWs[k * Dc + i];
                #pragma unroll 8
                for (int k = 0; k < Dc; k++)
                    al += m_s[r * Dc + k] * wcWs[(Dc + k) * Dc + i];
                float ch = al * zh + (1.0f - al) * xh_s[r * Dc + i];
                float mm = m_s[r * Dc + i];
                float cc = mm * x_s[r * Dc + i] + (1.0f - mm) * ch;
                inp_s[r * 128 + i] = cc;
                inp_s[r * 128 + 64 + i] = mm;
                out_imp[((long)(b0 + r) * Tc + t) * Dc + i] = cc;
            }
        }
        __syncthreads();

        // ---- z = [c_c|m] @ lstm_k + h @ lstm_rk + b; gates; state update ----
        float a0[MB], a1[MB], a2[MB], a3[MB];
        #pragma unroll
        for (int r = 0; r < MB; r++) {
            a0[r] = bls0; a1[r] = bls1; a2[r] = bls2; a3[r] = bls3;
        }
        {
            const float* W = lstm_k;   // [128][1024]
            #pragma unroll 2
            for (int k = 0; k < 128; k++) {
                float w0 = __ldg(&W[k * 1024 + tid]);
                float w1 = __ldg(&W[k * 1024 + 256 + tid]);
                float w2 = __ldg(&W[k * 1024 + 512 + tid]);
                float w3 = __ldg(&W[k * 1024 + 768 + tid]);
                #pragma unroll
                for (int r = 0; r < MB; r++) {
                    float a = inp_s[r * 128 + k];
                    a0[r] += a * w0; a1[r] += a * w1;
                    a2[r] += a * w2; a3[r] += a * w3;
                }
            }
            const float* Wr = lstm_rk; // [256][1024]
            #pragma unroll 2
            for (int k = 0; k < 256; k++) {
                float w0 = __ldg(&Wr[k * 1024 + tid]);
                float w1 = __ldg(&Wr[k * 1024 + 256 + tid]);
                float w2 = __ldg(&Wr[k * 1024 + 512 + tid]);
                float w3 = __ldg(&Wr[k * 1024 + 768 + tid]);
                #pragma unroll
                for (int r = 0; r < MB; r++) {
                    float a = h_s[r * Hc + k];
                    a0[r] += a * w0; a1[r] += a * w1;
                    a2[r] += a * w2; a3[r] += a * w3;
                }
            }
        }
        __syncthreads();  // all threads done reading h_s before overwrite
        #pragma unroll
        for (int r = 0; r < MB; r++) {
            float ig = sigf(a0[r]);
            float fg = sigf(a1[r]);
            float gg = tanhf(a2[r]);
            float og = sigf(a3[r]);
            float cn = fg * c_reg[r] + ig * gg;
            c_reg[r] = cn;
            h_s[r * Hc + tid] = og * tanhf(cn);
        }
        __syncthreads();
    }

    // ---- y = h @ out_W + out_b ----
    {
        float ow = __ldg(&out_W[tid]);
        int lane = tid & 31, w = tid >> 5;
        for (int r = 0; r < MB; r++) {
            float p = h_s[r * Hc + tid] * ow;
            #pragma unroll
            for (int off = 16; off > 0; off >>= 1)
                p += __shfl_xor_sync(0xffffffffu, p, off);
            if (lane == 0) red_s[w] = p;
            __syncthreads();
            if (tid == 0) {
                float s = out_b[0];
                #pragma unroll
                for (int q = 0; q < 8; q++) s += red_s[q];
                out_y[b0 + r] = s;
            }
            __syncthreads();
        }
    }
}

extern "C" void kernel_launch(void* const* d_in, const int* in_sizes, int n_in,
                              void* d_out, int out_size)
{
    const float* values = (const float*)d_in[0];
    const float* masks  = (const float*)d_in[1];
    const float* deltas = (const float*)d_in[2];
    const float* td_h_W = (const float*)d_in[3];
    const float* td_h_b = (const float*)d_in[4];
    const float* td_x_W = (const float*)d_in[5];
    const float* td_x_b = (const float*)d_in[6];
    const float* hist_W = (const float*)d_in[7];
    const float* hist_b = (const float*)d_in[8];
    const float* fr_W   = (const float*)d_in[9];
    const float* fr_b   = (const float*)d_in[10];
    const float* wc_W   = (const float*)d_in[11];
    const float* wc_b   = (const float*)d_in[12];
    const float* lstm_k  = (const float*)d_in[13];
    const float* lstm_rk = (const float*)d_in[14];
    const float* lstm_b  = (const float*)d_in[15];
    const float* out_W  = (const float*)d_in[16];
    const float* out_b  = (const float*)d_in[17];
    float* out = (float*)d_out;

    static bool attr_set = false;
    if (!attr_set) {
        cudaFuncSetAttribute(rits_kernel,
                             cudaFuncAttributeMaxDynamicSharedMemorySize, SMEM_BYTES);
        attr_set = true;
    }
    rits_kernel<<<Bc / MB, NT, SMEM_BYTES>>>(
        values, masks, deltas, td_h_W, td_h_b, td_x_W, td_x_b,
        hist_W, hist_b, fr_W, fr_b, wc_W, wc_b,
        lstm_k, lstm_rk, lstm_b, out_W, out_b, out);
}

// round 3
// speedup vs baseline: 1.5471x; 1.5471x over previous
#include <cuda_runtime.h>
#include <math.h>

// RITS recurrent imputation. B=1024, T=128, D=64, H=256.
// 512 threads/CTA: thread = (gate-pair gp, hidden col htid).
//   gp0 owns gates (i,g), gp1 owns gates (f,o) + cell state.
// Big LSTM GEMM uses packed fma.rn.f32x2 over row-pairs with transposed
// activations (inp_t[128][8], h_t[256][8]) so LDS.128 delivers 4 rows.

#define Bc 1024
#define Tc 128
#define Dc 64
#define Hc 256
#define MB 8
#define NT 512

// shared layout (floats)
#define OF_TDHWT 0                      // 64x256 (transposed td_h_W)
#define OF_HISTW (OF_TDHWT + 16384)     // 256x64
#define OF_TXWT  (OF_HISTW + 16384)     // 64x64 (transposed td_x_W)
#define OF_FRWT  (OF_TXWT + 4096)       // 64x64 (transposed fr_W)
#define OF_WCW   (OF_FRWT + 4096)       // 128x64
#define OF_BHS   (OF_WCW + 8192)        // 256
#define OF_BXS   (OF_BHS + 256)         // 64
#define OF_BHIST (OF_BXS + 64)          // 64
#define OF_BFR   (OF_BHIST + 64)        // 64
#define OF_BWC   (OF_BFR + 64)          // 64
#define OF_HT    (OF_BWC + 64)          // h_t[256][8]  (col-major state)
#define OF_X     (OF_HT + 2048)         // 8x64
#define OF_M     (OF_X + 512)           // 8x64
#define OF_D     (OF_M + 512)           // 8x64
#define OF_INPT  (OF_D + 512)           // inp_t[128][8]
#define OF_SCR   (OF_INPT + 1024)       // 2048: xh|xc|gx during pre-GEMM, p_s/red after
#define SMEM_FLOATS (OF_SCR + 2048)
#define SMEM_BYTES (SMEM_FLOATS * 4)    // 225,280 B

typedef unsigned long long u64;

__device__ __forceinline__ u64 pack2(float a, float b) {
    u64 r; asm("mov.b64 %0,{%1,%2};" : "=l"(r) : "f"(a), "f"(b)); return r;
}
__device__ __forceinline__ void unpack2(u64 v, float& a, float& b) {
    asm("mov.b64 {%0,%1},%2;" : "=f"(a), "=f"(b) : "l"(v));
}
__device__ __forceinline__ void fma2(u64& acc, u64 a, u64 b) {
    asm("fma.rn.f32x2 %0, %1, %2, %0;" : "+l"(acc) : "l"(a), "l"(b));
}
__device__ __forceinline__ float sigf(float x) {
    return __fdividef(1.0f, 1.0f + __expf(-x));
}

extern "C" __global__ void __launch_bounds__(NT, 1)
rits_kernel(const float* __restrict__ values, const float* __restrict__ masks,
            const float* __restrict__ deltas,
            const float* __restrict__ td_h_W, const float* __restrict__ td_h_b,
            const float* __restrict__ td_x_W, const float* __restrict__ td_x_b,
            const float* __restrict__ hist_W, const float* __restrict__ hist_b,
            const float* __restrict__ fr_W, const float* __restrict__ fr_b,
            const float* __restrict__ wc_W, const float* __restrict__ wc_b,
            const float* __restrict__ lstm_k, const float* __restrict__ lstm_rk,
            const float* __restrict__ lstm_b,
            const float* __restrict__ out_W, const float* __restrict__ out_b,
            float* __restrict__ out)
{
    extern __shared__ float sm[];
    float* tdhWT = sm + OF_TDHWT;
    float* histWs = sm + OF_HISTW;
    float* txWT = sm + OF_TXWT;
    float* frWT = sm + OF_FRWT;
    float* wcWs = sm + OF_WCW;
    float* bhs = sm + OF_BHS;
    float* bxs = sm + OF_BXS;
    float* bhist = sm + OF_BHIST;
    float* bfr = sm + OF_BFR;
    float* bwc = sm + OF_BWC;
    float* h_t = sm + OF_HT;      // [256][8]
    float* x_s = sm + OF_X;
    float* m_s = sm + OF_M;
    float* d_s = sm + OF_D;
    float* inp_t = sm + OF_INPT;  // [128][8]
    float* xh_s = sm + OF_SCR;        // 512
    float* xc_s = sm + OF_SCR + 512;  // 512
    float* gx_s = sm + OF_SCR + 1024; // 512
    float* p_s  = sm + OF_SCR;        // 2048 (aliases xh/xc/gx after GEMM)

    const int tid = threadIdx.x;
    const int gp = tid >> 8;          // 0: gates (i,g)  1: gates (f,o)
    const int htid = tid & 255;       // hidden column
    const int b0 = blockIdx.x * MB;

    // ---- preload small weights into SMEM (transposed where needed) ----
    for (int idx = tid; idx < Hc * Dc; idx += NT) {   // td_h_W [H,D] -> [D,H]
        int j = idx >> 6, k = idx & 63;
        tdhWT[k * Hc + j] = td_h_W[idx];
    }
    for (int idx = tid; idx < Hc * Dc; idx += NT)     // hist_W [H,D] as-is
        histWs[idx] = hist_W[idx];
    for (int idx = tid; idx < Dc * Dc; idx += NT) {   // td_x_W -> T
        int i = idx >> 6, k = idx & 63;
        txWT[k * Dc + i] = td_x_W[idx];
    }
    for (int idx = tid; idx < Dc * Dc; idx += NT) {   // fr_W -> T
        int i = idx >> 6, k = idx & 63;
        frWT[k * Dc + i] = fr_W[idx];
    }
    for (int idx = tid; idx < 2 * Dc * Dc; idx += NT) // wc_W as-is
        wcWs[idx] = wc_W[idx];
    if (tid < 256) bhs[tid] = td_h_b[tid];
    if (tid >= 256 && tid < 320) {
        int q = tid - 256;
        bxs[q] = td_x_b[q];
        bhist[q] = hist_b[q];
        bfr[q] = fr_b[q];
        bwc[q] = wc_b[q];
    }
    // init state h_t = 0
    for (int idx = tid; idx < Hc * MB; idx += NT) h_t[idx] = 0.0f;
    float c_reg[MB];
    #pragma unroll
    for (int r = 0; r < MB; r++) c_reg[r] = 0.0f;
    __syncthreads();

    // gate columns for this thread
    const int col0 = htid + gp * 256;        // i (gp0) / f (gp1)
    const int col1 = htid + 512 + gp * 256;  // g (gp0) / o (gp1)
    const float bls0 = lstm_b[col0];
    const float bls1 = lstm_b[col1];

    const int rL = tid >> 6;      // row slot 0..7 for D-wide phases
    const int iL = tid & 63;      // feature col

    float* out_y = out;
    float* out_imp = out + Bc;

    for (int t = 0; t < Tc; t++) {
        // ---- phase 1: load x, m, d (one element each) ----
        {
            long gi = ((long)(b0 + rL) * Tc + t) * Dc + iL;
            x_s[tid] = values[gi];
            m_s[tid] = masks[gi];
            d_s[tid] = deltas[gi];
        }
        __syncthreads();

        // ---- phase 2: gamma_h (scale h_t) + gamma_x ----
        {
            // gamma_h: 4 rows per thread, col htid
            #pragma unroll
            for (int rr = 0; rr < 4; rr++) {
                int r = gp * 4 + rr;
                float s = bhs[htid];
                #pragma unroll 16
                for (int k = 0; k < Dc; k++)
                    s += d_s[r * Dc + k] * tdhWT[k * Hc + htid];
                float gh = __expf(-fmaxf(s, 0.0f));
                h_t[htid * MB + r] *= gh;
            }
            // gamma_x: one (r, i) per thread
            float s2 = bxs[iL];
            #pragma unroll 16
            for (int k = 0; k < Dc; k++)
                s2 += d_s[rL * Dc + k] * txWT[k * Dc + iL];
            gx_s[rL * Dc + iL] = __expf(-fmaxf(s2, 0.0f));
        }
        __syncthreads();

        // ---- phase 3: x_h = h @ hist_W + b; x_c ----
        {
            float s = bhist[iL];
            #pragma unroll 16
            for (int j = 0; j < Hc; j++)
                s += h_t[j * MB + rL] * histWs[j * Dc + iL];
            float mm = m_s[rL * Dc + iL];
            xh_s[rL * Dc + iL] = s;
            xc_s[rL * Dc + iL] = mm * x_s[rL * Dc + iL] + (1.0f - mm) * s;
        }
        __syncthreads();

        // ---- phase 4: z_h, alpha, c_h, c_c, imputation, build inp_t ----
        {
            float zh = bfr[iL];
            #pragma unroll 16
            for (int k = 0; k < Dc; k++)
                zh += xc_s[rL * Dc + k] * frWT[k * Dc + iL];
            float al = bwc[iL];
            #pragma unroll 16
            for (int k = 0; k < Dc; k++)
                al += gx_s[rL * Dc + k] * wcWs[k * Dc + iL];
            #pragma unroll 16
            for (int k = 0; k < Dc; k++)
                al += m_s[rL * Dc + k] * wcWs[(Dc + k) * Dc + iL];
            float ch = al * zh + (1.0f - al) * xh_s[rL * Dc + iL];
            float mm = m_s[rL * Dc + iL];
            float cc = mm * x_s[rL * Dc + iL] + (1.0f - mm) * ch;
            inp_t[iL * MB + rL] = cc;            // transposed [k][r]
            inp_t[(Dc + iL) * MB + rL] = mm;
            out_imp[((long)(b0 + rL) * Tc + t) * Dc + iL] = cc;
        }
        __syncthreads();

        // ---- phase 5: big GEMM  z = [c_c|m] @ lstm_k + h @ lstm_rk + b ----
        // packed f32x2 over row-pairs; acc A0 = gate col0, A1 = gate col1
        u64 A0[4], A1[4];
        #pragma unroll
        for (int p = 0; p < 4; p++) { A0[p] = pack2(bls0, bls0); A1[p] = pack2(bls1, bls1); }
        {
            const float* W = lstm_k;   // [128][1024]
            #pragma unroll 4
            for (int k = 0; k < 128; k++) {
                float w0 = __ldg(&W[k * 1024 + col0]);
                float w1 = __ldg(&W[k * 1024 + col1]);
                ulonglong2 v0 = *(const ulonglong2*)(inp_t + k * MB);
                ulonglong2 v1 = *(const ulonglong2*)(inp_t + k * MB + 4);
                u64 w00 = pack2(w0, w0), w11 = pack2(w1, w1);
                fma2(A0[0], v0.x, w00); fma2(A0[1], v0.y, w00);
                fma2(A0[2], v1.x, w00); fma2(A0[3], v1.y, w00);
                fma2(A1[0], v0.x, w11); fma2(A1[1], v0.y, w11);
                fma2(A1[2], v1.x, w11); fma2(A1[3], v1.y, w11);
            }
            const float* Wr = lstm_rk; // [256][1024]
            #pragma unroll 4
            for (int k = 0; k < 256; k++) {
                float w0 = __ldg(&Wr[k * 1024 + col0]);
                float w1 = __ldg(&Wr[k * 1024 + col1]);
                ulonglong2 v0 = *(const ulonglong2*)(h_t + k * MB);
                ulonglong2 v1 = *(const ulonglong2*)(h_t + k * MB + 4);
                u64 w00 = pack2(w0, w0), w11 = pack2(w1, w1);
                fma2(A0[0], v0.x, w00); fma2(A0[1], v0.y, w00);
                fma2(A0[2], v1.x, w00); fma2(A0[3], v1.y, w00);
                fma2(A1[0], v0.x, w11); fma2(A1[1], v0.y, w11);
                fma2(A1[2], v1.x, w11); fma2(A1[3], v1.y, w11);
            }
        }
        // gp0: p = sigmoid(z_i) * tanh(z_g)  -> p_s (aliases dead scratch)
        if (gp == 0) {
            float4 o0, o1;
            float za, zb, ga, gb;
            unpack2(A0[0], za, zb); unpack2(A1[0], ga, gb);
            o0.x = sigf(za) * tanhf(ga); o0.y = sigf(zb) * tanhf(gb);
            unpack2(A0[1], za, zb); unpack2(A1[1], ga, gb);
            o0.z = sigf(za) * tanhf(ga); o0.w = sigf(zb) * tanhf(gb);
            unpack2(A0[2], za, zb); unpack2(A1[2], ga, gb);
            o1.x = sigf(za) * tanhf(ga); o1.y = sigf(zb) * tanhf(gb);
            unpack2(A0[3], za, zb); unpack2(A1[3], ga, gb);
            o1.z = sigf(za) * tanhf(ga); o1.w = sigf(zb) * tanhf(gb);
            *(float4*)(p_s + htid * MB) = o0;
            *(float4*)(p_s + htid * MB + 4) = o1;
        }
        __syncthreads();  // GEMM reads of h_t done; p_s visible

        // gp1: cell update c = sig(f)*c + p; h = sig(o)*tanh(c) -> h_t
        if (gp == 1) {
            float4 pr0 = *(const float4*)(p_s + htid * MB);
            float4 pr1 = *(const float4*)(p_s + htid * MB + 4);
            float pf[8] = {pr0.x, pr0.y, pr0.z, pr0.w, pr1.x, pr1.y, pr1.z, pr1.w};
            float zf[8], zo[8];
            unpack2(A0[0], zf[0], zf[1]); unpack2(A0[1], zf[2], zf[3]);
            unpack2(A0[2], zf[4], zf[5]); unpack2(A0[3], zf[6], zf[7]);
            unpack2(A1[0], zo[0], zo[1]); unpack2(A1[1], zo[2], zo[3]);
            unpack2(A1[2], zo[4], zo[5]); unpack2(A1[3], zo[6], zo[7]);
            float hv[8];
            #pragma unroll
            for (int r = 0; r < MB; r++) {
                float cn = sigf(zf[r]) * c_reg[r] + pf[r];
                c_reg[r] = cn;
                hv[r] = sigf(zo[r]) * tanhf(cn);
            }
            float4 h0 = {hv[0], hv[1], hv[2], hv[3]};
            float4 h1 = {hv[4], hv[5], hv[6], hv[7]};
            *(float4*)(h_t + htid * MB) = h0;
            *(float4*)(h_t + htid * MB + 4) = h1;
        }
        // next iteration's phase-1 sync orders h_t writes before phase-2 reads
        __syncthreads();
    }

    // ---- y = h @ out_W + out_b ----
    {
        float* red = p_s;  // scratch
        float ow = (gp == 0) ? __ldg(&out_W[htid]) : 0.0f;
        int lane = tid & 31, w = tid >> 5;  // 16 warps
        for (int r = 0; r < MB; r++) {
            float v = (gp == 0) ? h_t[htid * MB + r] * ow : 0.0f;
            #pragma unroll
            for (int off = 16; off > 0; off >>= 1)
                v += __shfl_xor_sync(0xffffffffu, v, off);
            if (lane == 0) red[w] = v;
            __syncthreads();
            if (tid == 0) {
                float s = out_b[0];
                #pragma unroll
                for (int q = 0; q < 16; q++) s += red[q];
                out_y[b0 + r] = s;
            }
            __syncthreads();
        }
    }
}

extern "C" void kernel_launch(void* const* d_in, const int* in_sizes, int n_in,
                              void* d_out, int out_size)
{
    const float* values = (const float*)d_in[0];
    const float* masks  = (const float*)d_in[1];
    const float* deltas = (const float*)d_in[2];
    const float* td_h_W = (const float*)d_in[3];
    const float* td_h_b = (const float*)d_in[4];
    const float* td_x_W = (const float*)d_in[5];
    const float* td_x_b = (const float*)d_in[6];
    const float* hist_W = (const float*)d_in[7];
    const float* hist_b = (const float*)d_in[8];
    const float* fr_W   = (const float*)d_in[9];
    const float* fr_b   = (const float*)d_in[10];
    const float* wc_W   = (const float*)d_in[11];
    const float* wc_b   = (const float*)d_in[12];
    const float* lstm_k  = (const float*)d_in[13];
    const float* lstm_rk = (const float*)d_in[14];
    const float* lstm_b  = (const float*)d_in[15];
    const float* out_W  = (const float*)d_in[16];
    const float* out_b  = (const float*)d_in[17];
    float* out = (float*)d_out;

    static bool attr_set = false;
    if (!attr_set) {
        cudaFuncSetAttribute(rits_kernel,
                             cudaFuncAttributeMaxDynamicSharedMemorySize, SMEM_BYTES);
        attr_set = true;
    }
    rits_kernel<<<Bc / MB, NT, SMEM_BYTES>>>(
        values, masks, deltas, td_h_W, td_h_b, td_x_W, td_x_b,
        hist_W, hist_b, fr_W, fr_b, wc_W, wc_b,
        lstm_k, lstm_rk, lstm_b, out_W, out_b, out);
}